// round 5
// baseline (speedup 1.0000x reference)
#include <cuda_runtime.h>
#include <cuda_fp16.h>
#include <cstdint>
#include <math.h>

#define NEXP 16
#define TOPK 4
#define HDIM 2048
#define IDIM 2048
#define TMAX 4096
#define ALPHA 1.702f
#define LIMIT 7.0f
#define NKB 64     // 2048 / 32
#define KHALF 32   // halfs of K per stage
#define LDK 80     // bytes per padded row (64B data + 16B pad)

__device__ int    g_cnt[NEXP];
__device__ int    g_tok[NEXP * TMAX];
__device__ int    g_tslot[TMAX * TOPK];
__device__ float  g_twt[TMAX * TOPK];
__device__ __half g_xh[(size_t)TMAX * HDIM];
__device__ __half g_w1h[(size_t)NEXP * 2 * IDIM * HDIM];  // [e][n=4096][k=2048]
__device__ __half g_w2h[(size_t)NEXP * HDIM * IDIM];      // [e][n=2048][k=2048]
__device__ __half g_acth[(size_t)NEXP * TMAX * IDIM];     // [e][slot][i]
__device__ float  g_part[(size_t)NEXP * TMAX * HDIM];     // [e][slot][h]

// ---------------- helpers ----------------
__device__ __forceinline__ void cp16(const void* smem_dst, const void* gsrc, bool pred) {
  uint32_t d = (uint32_t)__cvta_generic_to_shared(smem_dst);
  int sz = pred ? 16 : 0;
  asm volatile("cp.async.cg.shared.global [%0], [%1], 16, %2;" :: "r"(d), "l"(gsrc), "r"(sz));
}
__device__ __forceinline__ void cp_commit() { asm volatile("cp.async.commit_group;"); }

__device__ __forceinline__ void mma16(float* c, const uint32_t* a, const uint32_t* b) {
  asm volatile(
      "mma.sync.aligned.m16n8k16.row.col.f32.f16.f16.f32 "
      "{%0,%1,%2,%3}, {%4,%5,%6,%7}, {%8,%9}, {%0,%1,%2,%3};"
      : "+f"(c[0]), "+f"(c[1]), "+f"(c[2]), "+f"(c[3])
      : "r"(a[0]), "r"(a[1]), "r"(a[2]), "r"(a[3]), "r"(b[0]), "r"(b[1]));
}
__device__ __forceinline__ uint32_t lds32(const char* smem, uint32_t off) {
  return *(const uint32_t*)(smem + off);
}

// ---------------- router ----------------
__global__ void zero_cnt_kernel() { if (threadIdx.x < NEXP) g_cnt[threadIdx.x] = 0; }

__global__ __launch_bounds__(256) void router_kernel(const float* __restrict__ x,
                                                     const float* __restrict__ rw,
                                                     const float* __restrict__ rb) {
  int warp = threadIdx.x >> 5, lane = threadIdx.x & 31;
  int t = blockIdx.x * 8 + warp;
  float acc[NEXP];
#pragma unroll
  for (int e = 0; e < NEXP; e++) acc[e] = 0.f;
  const float* xr = x + (size_t)t * HDIM;
  for (int h = lane; h < HDIM; h += 32) {
    float xv = xr[h];
#pragma unroll
    for (int e = 0; e < NEXP; e++) acc[e] = fmaf(xv, rw[e * HDIM + h], acc[e]);
  }
#pragma unroll
  for (int e = 0; e < NEXP; e++)
#pragma unroll
    for (int o = 16; o > 0; o >>= 1) acc[e] += __shfl_xor_sync(0xffffffffu, acc[e], o);
  if (lane == 0) {
    float v[NEXP];
#pragma unroll
    for (int e = 0; e < NEXP; e++) v[e] = acc[e] + rb[e];
    int ids[TOPK]; float vals[TOPK];
#pragma unroll
    for (int j = 0; j < TOPK; j++) {
      float best = -1e30f; int bi = 0;
#pragma unroll
      for (int e = 0; e < NEXP; e++)
        if (v[e] > best) { best = v[e]; bi = e; }
      ids[j] = bi; vals[j] = best; v[bi] = -1e30f;
    }
    float m = vals[0], s = 0.f, w[TOPK];
#pragma unroll
    for (int j = 0; j < TOPK; j++) { w[j] = expf(vals[j] - m); s += w[j]; }
    float inv = 1.f / s;
#pragma unroll
    for (int j = 0; j < TOPK; j++) {
      int e = ids[j];
      int p = atomicAdd(&g_cnt[e], 1);
      g_tok[e * TMAX + p] = t;
      g_tslot[t * TOPK + j] = e * TMAX + p;
      g_twt[t * TOPK + j] = w[j] * inv;
    }
  }
}

// ---------------- prep ----------------
__global__ __launch_bounds__(256) void cvtx_kernel(const float* __restrict__ x) {
  size_t i = ((size_t)blockIdx.x * 256 + threadIdx.x);
  float4 v = ((const float4*)x)[i];
  __half2 h0 = __floats2half2_rn(v.x, v.y);
  __half2 h1 = __floats2half2_rn(v.z, v.w);
  uint2 o = { *(uint32_t*)&h0, *(uint32_t*)&h1 };
  ((uint2*)g_xh)[i] = o;
}

// src: [e][R(k)][C(n)] fp32  ->  dst: [e][C(n)][R(k)] fp16
__global__ __launch_bounds__(256) void transpose_h_kernel(const float* __restrict__ src,
                                                          __half* __restrict__ dst,
                                                          int R, int C) {
  __shared__ float tile[32][33];
  int e = blockIdx.z;
  const float* s = src + (size_t)e * R * C;
  __half* d = dst + (size_t)e * R * C;
  int r0 = blockIdx.y * 32, c0 = blockIdx.x * 32;
  int tr = threadIdx.x >> 3, tc = (threadIdx.x & 7) << 2;
  float4 v = *(const float4*)(s + (size_t)(r0 + tr) * C + c0 + tc);
  tile[tr][tc] = v.x; tile[tr][tc + 1] = v.y; tile[tr][tc + 2] = v.z; tile[tr][tc + 3] = v.w;
  __syncthreads();
  __half2 h0 = __floats2half2_rn(tile[tc][tr],     tile[tc + 1][tr]);
  __half2 h1 = __floats2half2_rn(tile[tc + 2][tr], tile[tc + 3][tr]);
  uint2 o = { *(uint32_t*)&h0, *(uint32_t*)&h1 };
  *(uint2*)(d + (size_t)(c0 + tr) * R + r0 + tc) = o;
}

// ---------------- GEMM1: X @ w1 (gate|up) -> clipped GLU -> g_acth ----------------
// stage s at s*30720: A [128 x LDK] at +0, B [256 x LDK] at +10240
#define STG1 30720
#define SMEM1 (4 * STG1 + 512)

__global__ __launch_bounds__(512, 1) void gemm1_kernel(const float* __restrict__ b1) {
  int e = blockIdx.z;
  int cnt = g_cnt[e];
  int m0 = blockIdx.x * 128;
  if (m0 >= cnt) return;
  int n0 = blockIdx.y * 128;

  extern __shared__ __align__(16) char smem[];
  int* toks = (int*)(smem + 4 * STG1);
  int tid = threadIdx.x, w = tid >> 5, lane = tid & 31;
  int g = lane >> 2, tq = lane & 3;

  if (tid < 128) toks[tid] = (m0 + tid < cnt) ? g_tok[e * TMAX + m0 + tid] : -1;
  __syncthreads();

  // A: each thread owns one 16B chunk: row = tid>>2 (0..127), chunk = tid&3
  int ar = tid >> 2, ch = tid & 3;
  int tok = toks[ar];
  bool apred = tok >= 0;
  const __half* asrc = g_xh + (size_t)(tok < 0 ? 0 : tok) * HDIM + ch * 8;
  uint32_t adst = ar * LDK + ch * 16;

  const __half* w1e = g_w1h + (size_t)e * 4096 * 2048;
  const __half* bsrc[2]; uint32_t bdst[2];
#pragma unroll
  for (int q = 0; q < 2; q++) {
    int idx = tid + q * 512;           // 0..1023
    int row = idx >> 2, ch2 = idx & 3; // row 0..255
    int n = (row < 128) ? (n0 + row) : (2048 + n0 + row - 128);
    bsrc[q] = w1e + (size_t)n * 2048 + ch2 * 8;
    bdst[q] = 10240 + row * LDK + ch2 * 16;
  }

  auto ld = [&](int kb) {
    char* base = smem + (kb & 3) * STG1;
    int ko = kb * KHALF;
    cp16(base + adst, asrc + ko, apred);
    cp16(base + bdst[0], bsrc[0] + ko, true);
    cp16(base + bdst[1], bsrc[1] + ko, true);
    cp_commit();
  };

  float cg[2][4][4], cu[2][4][4];
#pragma unroll
  for (int mi = 0; mi < 2; mi++)
#pragma unroll
    for (int ni = 0; ni < 4; ni++)
#pragma unroll
      for (int q = 0; q < 4; q++) { cg[mi][ni][q] = 0.f; cu[mi][ni][q] = 0.f; }

  int wm = (w & 3) * 32, wn = (w >> 2) * 32;
  ld(0); ld(1); ld(2);

  for (int kb = 0; kb < NKB; kb++) {
    if (kb < NKB - 2)       asm volatile("cp.async.wait_group 2;");
    else if (kb == NKB - 2) asm volatile("cp.async.wait_group 1;");
    else                    asm volatile("cp.async.wait_group 0;");
    __syncthreads();
    if (kb + 3 < NKB) ld(kb + 3);
    const char* Ab = smem + (kb & 3) * STG1;
    const char* Bb = Ab + 10240;
#pragma unroll
    for (int kk = 0; kk < 2; kk++) {
      uint32_t kob = kk * 32 + tq * 4;
      uint32_t a[2][4];
#pragma unroll
      for (int mi = 0; mi < 2; mi++) {
        uint32_t base = (wm + mi * 16 + g) * LDK + kob;
        a[mi][0] = lds32(Ab, base);
        a[mi][1] = lds32(Ab, base + 8 * LDK);
        a[mi][2] = lds32(Ab, base + 16);
        a[mi][3] = lds32(Ab, base + 8 * LDK + 16);
      }
#pragma unroll
      for (int ni = 0; ni < 4; ni++) {
        uint32_t nb = (wn + ni * 8 + g) * LDK + kob;
        uint32_t bg[2], bu[2];
        bg[0] = lds32(Bb, nb);
        bg[1] = lds32(Bb, nb + 16);
        bu[0] = lds32(Bb, nb + 128 * LDK);
        bu[1] = lds32(Bb, nb + 128 * LDK + 16);
#pragma unroll
        for (int mi = 0; mi < 2; mi++) {
          mma16(cg[mi][ni], a[mi], bg);
          mma16(cu[mi][ni], a[mi], bu);
        }
      }
    }
    __syncthreads();
  }

  const float* b1e = b1 + (size_t)e * 4096;
#pragma unroll
  for (int ni = 0; ni < 4; ni++) {
    int col = n0 + wn + ni * 8 + 2 * tq;
    float bg0 = b1e[col], bg1 = b1e[col + 1];
    float bu0 = b1e[2048 + col], bu1 = b1e[2048 + col + 1];
#pragma unroll
    for (int mi = 0; mi < 2; mi++) {
#pragma unroll
      for (int rr = 0; rr < 2; rr++) {
        int rl = wm + mi * 16 + rr * 8 + g;
        if (m0 + rl >= cnt) continue;
        float gv0 = cg[mi][ni][rr * 2 + 0] + bg0;
        float gv1 = cg[mi][ni][rr * 2 + 1] + bg1;
        float uv0 = cu[mi][ni][rr * 2 + 0] + bu0;
        float uv1 = cu[mi][ni][rr * 2 + 1] + bu1;
        gv0 = fminf(gv0, LIMIT); gv1 = fminf(gv1, LIMIT);
        uv0 = fminf(fmaxf(uv0, -LIMIT), LIMIT);
        uv1 = fminf(fmaxf(uv1, -LIMIT), LIMIT);
        float a0 = (uv0 + 1.f) * gv0 / (1.f + __expf(-ALPHA * gv0));
        float a1 = (uv1 + 1.f) * gv1 / (1.f + __expf(-ALPHA * gv1));
        __half2 h = __floats2half2_rn(a0, a1);
        *(__half2*)(g_acth + ((size_t)e * TMAX + m0 + rl) * 2048 + col) = h;
      }
    }
  }
}

// ---------------- GEMM2: acts @ w2 -> g_part ----------------
// stage s at s*20480: A [128 x LDK] at +0, B [128 x LDK] at +10240
#define STG2 20480
#define SMEM2 (4 * STG2)

__global__ __launch_bounds__(256, 2) void gemm2_kernel() {
  int e = blockIdx.z;
  int cnt = g_cnt[e];
  int m0 = blockIdx.x * 128;
  if (m0 >= cnt) return;
  int n0 = blockIdx.y * 128;

  extern __shared__ __align__(16) char smem[];
  int tid = threadIdx.x, w = tid >> 5, lane = tid & 31;
  int g = lane >> 2, tq = lane & 3;

  const __half* acte = g_acth + (size_t)e * TMAX * 2048;
  const __half* w2e = g_w2h + (size_t)e * 2048 * 2048;

  const __half* asrc[2]; uint32_t adst[2]; bool apred[2];
  const __half* bsrc[2]; uint32_t bdst[2];
#pragma unroll
  for (int q = 0; q < 2; q++) {
    int idx = tid + q * 256;           // 0..511
    int row = idx >> 2, ch = idx & 3;  // row 0..127
    apred[q] = (m0 + row) < cnt;
    asrc[q] = acte + (size_t)(m0 + row) * 2048 + ch * 8;
    adst[q] = row * LDK + ch * 16;
    bsrc[q] = w2e + (size_t)(n0 + row) * 2048 + ch * 8;
    bdst[q] = 10240 + row * LDK + ch * 16;
  }

  auto ld = [&](int kb) {
    char* base = smem + (kb & 3) * STG2;
    int ko = kb * KHALF;
#pragma unroll
    for (int q = 0; q < 2; q++) {
      cp16(base + adst[q], asrc[q] + ko, apred[q]);
      cp16(base + bdst[q], bsrc[q] + ko, true);
    }
    cp_commit();
  };

  float cc[2][8][4];
#pragma unroll
  for (int mi = 0; mi < 2; mi++)
#pragma unroll
    for (int ni = 0; ni < 8; ni++)
#pragma unroll
      for (int q = 0; q < 4; q++) cc[mi][ni][q] = 0.f;

  int wm = (w & 3) * 32, wn = (w >> 2) * 64;
  ld(0); ld(1); ld(2);

  for (int kb = 0; kb < NKB; kb++) {
    if (kb < NKB - 2)       asm volatile("cp.async.wait_group 2;");
    else if (kb == NKB - 2) asm volatile("cp.async.wait_group 1;");
    else                    asm volatile("cp.async.wait_group 0;");
    __syncthreads();
    if (kb + 3 < NKB) ld(kb + 3);
    const char* Ab = smem + (kb & 3) * STG2;
    const char* Bb = Ab + 10240;
#pragma unroll
    for (int kk = 0; kk < 2; kk++) {
      uint32_t kob = kk * 32 + tq * 4;
      uint32_t a[2][4];
#pragma unroll
      for (int mi = 0; mi < 2; mi++) {
        uint32_t base = (wm + mi * 16 + g) * LDK + kob;
        a[mi][0] = lds32(Ab, base);
        a[mi][1] = lds32(Ab, base + 8 * LDK);
        a[mi][2] = lds32(Ab, base + 16);
        a[mi][3] = lds32(Ab, base + 8 * LDK + 16);
      }
#pragma unroll
      for (int ni = 0; ni < 8; ni++) {
        uint32_t nb = (wn + ni * 8 + g) * LDK + kob;
        uint32_t b[2];
        b[0] = lds32(Bb, nb);
        b[1] = lds32(Bb, nb + 16);
#pragma unroll
        for (int mi = 0; mi < 2; mi++) mma16(cc[mi][ni], a[mi], b);
      }
    }
    __syncthreads();
  }

  float* parte = g_part + (size_t)e * TMAX * 2048;
#pragma unroll
  for (int mi = 0; mi < 2; mi++) {
#pragma unroll
    for (int rr = 0; rr < 2; rr++) {
      int rl = wm + mi * 16 + rr * 8 + g;
      if (m0 + rl >= cnt) continue;
      float* prow = parte + (size_t)(m0 + rl) * 2048 + n0;
#pragma unroll
      for (int ni = 0; ni < 8; ni++) {
        float2 v = { cc[mi][ni][rr * 2 + 0], cc[mi][ni][rr * 2 + 1] };
        *(float2*)(prow + wn + ni * 8 + 2 * tq) = v;
      }
    }
  }
}

// ---------------- gather ----------------
__global__ __launch_bounds__(256) void gather_kernel(const float* __restrict__ b2,
                                                     float* __restrict__ out) {
  int t = blockIdx.y;
  int h = blockIdx.x * 1024 + threadIdx.x * 4;
  float4 acc = {0.f, 0.f, 0.f, 0.f};
#pragma unroll
  for (int j = 0; j < TOPK; j++) {
    int sidx = g_tslot[t * TOPK + j];
    float wj = g_twt[t * TOPK + j];
    int e = sidx >> 12;
    float4 p = *(const float4*)(g_part + (size_t)sidx * 2048 + h);
    float4 b = *(const float4*)(b2 + (size_t)e * 2048 + h);
    acc.x += wj * (p.x + b.x);
    acc.y += wj * (p.y + b.y);
    acc.z += wj * (p.z + b.z);
    acc.w += wj * (p.w + b.w);
  }
  *(float4*)(out + (size_t)t * 2048 + h) = acc;
}

// ---------------- launch ----------------
extern "C" void kernel_launch(void* const* d_in, const int* in_sizes, int n_in,
                              void* d_out, int out_size) {
  (void)in_sizes; (void)n_in; (void)out_size;
  const float* hs = (const float*)d_in[0];
  const float* rw = (const float*)d_in[1];
  const float* rb = (const float*)d_in[2];
  const float* w1 = (const float*)d_in[3];
  const float* b1 = (const float*)d_in[4];
  const float* w2 = (const float*)d_in[5];
  const float* b2 = (const float*)d_in[6];
  float* out = (float*)d_out;

  void *pw1, *pw2;
  cudaGetSymbolAddress(&pw1, g_w1h);
  cudaGetSymbolAddress(&pw2, g_w2h);

  zero_cnt_kernel<<<1, 32>>>();
  router_kernel<<<TMAX / 8, 256>>>(hs, rw, rb);
  cvtx_kernel<<<(TMAX * HDIM) / 1024, 256>>>(hs);
  {
    dim3 g(4096 / 32, 2048 / 32, NEXP);
    transpose_h_kernel<<<g, 256>>>(w1, (__half*)pw1, 2048, 4096);
  }
  {
    dim3 g(2048 / 32, 2048 / 32, NEXP);
    transpose_h_kernel<<<g, 256>>>(w2, (__half*)pw2, 2048, 2048);
  }

  cudaFuncSetAttribute(gemm1_kernel, cudaFuncAttributeMaxDynamicSharedMemorySize, SMEM1);
  cudaFuncSetAttribute(gemm2_kernel, cudaFuncAttributeMaxDynamicSharedMemorySize, SMEM2);

  dim3 g1(TMAX / 128, 16, NEXP);   // x = m-tiles (fastest), y = n-tiles, z = expert
  gemm1_kernel<<<g1, 512, SMEM1>>>(b1);
  dim3 g2(TMAX / 128, 16, NEXP);
  gemm2_kernel<<<g2, 256, SMEM2>>>();
  dim3 gg(2, TMAX);
  gather_kernel<<<gg, 256>>>(b2, out);
}

// round 7
// speedup vs baseline: 1.3518x; 1.3518x over previous
#include <cuda_runtime.h>
#include <cuda_fp16.h>
#include <cstdint>
#include <math.h>

#define NEXP 16
#define TOPK 4
#define HDIM 2048
#define IDIM 2048
#define TMAX 4096
#define ALPHA 1.702f
#define LIMIT 7.0f
#define NKB 32     // 2048 / 64
#define KHALF 64   // k-halfs per stage
#define LDK 144    // A row pitch bytes

__device__ int    g_cnt[NEXP];
__device__ int    g_tok[NEXP * TMAX];
__device__ int    g_tslot[TMAX * TOPK];
__device__ float  g_twt[TMAX * TOPK];
__device__ __half g_xh[(size_t)TMAX * HDIM];
__device__ __half g_w1h[(size_t)NEXP * HDIM * 4096];   // fp16 w1, native [k][n] layout
__device__ __half g_w2h[(size_t)NEXP * IDIM * HDIM];   // fp16 w2, native [k][n] layout
__device__ __half g_acth[(size_t)NEXP * TMAX * IDIM];
__device__ float  g_part[(size_t)NEXP * TMAX * HDIM];

// ---------------- helpers ----------------
__device__ __forceinline__ void cp16(const void* smem_dst, const void* gsrc, bool pred) {
  uint32_t d = (uint32_t)__cvta_generic_to_shared(smem_dst);
  int sz = pred ? 16 : 0;
  asm volatile("cp.async.cg.shared.global [%0], [%1], 16, %2;" :: "r"(d), "l"(gsrc), "r"(sz));
}
__device__ __forceinline__ void cp_commit() { asm volatile("cp.async.commit_group;"); }

__device__ __forceinline__ void mma16(float* c, const uint32_t* a, const uint32_t* b) {
  asm volatile(
      "mma.sync.aligned.m16n8k16.row.col.f32.f16.f16.f32 "
      "{%0,%1,%2,%3}, {%4,%5,%6,%7}, {%8,%9}, {%0,%1,%2,%3};"
      : "+f"(c[0]), "+f"(c[1]), "+f"(c[2]), "+f"(c[3])
      : "r"(a[0]), "r"(a[1]), "r"(a[2]), "r"(a[3]), "r"(b[0]), "r"(b[1]));
}
__device__ __forceinline__ uint32_t lds32(const char* smem, uint32_t off) {
  return *(const uint32_t*)(smem + off);
}
__device__ __forceinline__ void ldmx4t(uint32_t& r0, uint32_t& r1, uint32_t& r2, uint32_t& r3,
                                       uint32_t addr) {
  asm volatile("ldmatrix.sync.aligned.m8n8.x4.trans.shared.b16 {%0,%1,%2,%3}, [%4];"
               : "=r"(r0), "=r"(r1), "=r"(r2), "=r"(r3) : "r"(addr));
}

// ---------------- router ----------------
__global__ void zero_cnt_kernel() { if (threadIdx.x < NEXP) g_cnt[threadIdx.x] = 0; }

__global__ __launch_bounds__(256) void router_kernel(const float* __restrict__ x,
                                                     const float* __restrict__ rw,
                                                     const float* __restrict__ rb) {
  int warp = threadIdx.x >> 5, lane = threadIdx.x & 31;
  int t = blockIdx.x * 8 + warp;
  float acc[NEXP];
#pragma unroll
  for (int e = 0; e < NEXP; e++) acc[e] = 0.f;
  const float* xr = x + (size_t)t * HDIM;
  for (int h = lane; h < HDIM; h += 32) {
    float xv = xr[h];
#pragma unroll
    for (int e = 0; e < NEXP; e++) acc[e] = fmaf(xv, rw[e * HDIM + h], acc[e]);
  }
#pragma unroll
  for (int e = 0; e < NEXP; e++)
#pragma unroll
    for (int o = 16; o > 0; o >>= 1) acc[e] += __shfl_xor_sync(0xffffffffu, acc[e], o);
  if (lane == 0) {
    float v[NEXP];
#pragma unroll
    for (int e = 0; e < NEXP; e++) v[e] = acc[e] + rb[e];
    int ids[TOPK]; float vals[TOPK];
#pragma unroll
    for (int j = 0; j < TOPK; j++) {
      float best = -1e30f; int bi = 0;
#pragma unroll
      for (int e = 0; e < NEXP; e++)
        if (v[e] > best) { best = v[e]; bi = e; }
      ids[j] = bi; vals[j] = best; v[bi] = -1e30f;
    }
    float m = vals[0], s = 0.f, w[TOPK];
#pragma unroll
    for (int j = 0; j < TOPK; j++) { w[j] = expf(vals[j] - m); s += w[j]; }
    float inv = 1.f / s;
#pragma unroll
    for (int j = 0; j < TOPK; j++) {
      int e = ids[j];
      int p = atomicAdd(&g_cnt[e], 1);
      g_tok[e * TMAX + p] = t;
      g_tslot[t * TOPK + j] = e * TMAX + p;
      g_twt[t * TOPK + j] = w[j] * inv;
    }
  }
}

// ---------------- prep: fp16 conversions (no transpose) ----------------
__global__ __launch_bounds__(256) void cvt_kernel(const float* __restrict__ src,
                                                  __half* __restrict__ dst) {
  size_t i = ((size_t)blockIdx.x * 256 + threadIdx.x);
  float4 v = ((const float4*)src)[i];
  __half2 h0 = __floats2half2_rn(v.x, v.y);
  __half2 h1 = __floats2half2_rn(v.z, v.w);
  uint2 o = { *(uint32_t*)&h0, *(uint32_t*)&h1 };
  ((uint2*)dst)[i] = o;
}

// ---------------- GEMM1: X @ w1 (gate|up) -> clipped GLU -> g_acth ----------------
// stage s at s*51200: A [128 x LDK=144B] at +0, B [64 k-rows x 512B] at +18432
#define STG1 51200
#define SMEM1 (2 * STG1 + 512)

__global__ __launch_bounds__(512, 1) void gemm1_kernel(const float* __restrict__ b1) {
  int e = blockIdx.z;
  int cnt = g_cnt[e];
  int m0 = blockIdx.x * 128;
  if (m0 >= cnt) return;
  int n0 = blockIdx.y * 128;

  extern __shared__ __align__(16) char smem[];
  uint32_t sbase = (uint32_t)__cvta_generic_to_shared(smem);
  int* toks = (int*)(smem + 2 * STG1);
  int tid = threadIdx.x, w = tid >> 5, lane = tid & 31;
  int g = lane >> 2, tq = lane & 3;

  if (tid < 128) toks[tid] = (m0 + tid < cnt) ? g_tok[e * TMAX + m0 + tid] : -1;
  __syncthreads();

  // A: 128 rows x 8 chunks (16B) = 1024 chunks; 2 per thread
  const __half* asrc[2]; uint32_t adst[2]; bool apred[2];
#pragma unroll
  for (int q = 0; q < 2; q++) {
    int idx = tid + q * 512;
    int row = idx >> 3, ch = idx & 7;
    int tok = toks[row];
    apred[q] = tok >= 0;
    asrc[q] = g_xh + (size_t)(tok < 0 ? 0 : tok) * HDIM + ch * 8;
    adst[q] = row * LDK + ch * 16;
  }

  // B: 64 k-rows x 32 chunks = 2048 chunks; 4 per thread
  const __half* w1e = g_w1h + (size_t)e * HDIM * 4096;
  const __half* bsrc[4]; uint32_t bdst[4];
#pragma unroll
  for (int q = 0; q < 4; q++) {
    int C = tid + q * 512;
    int k = C >> 5, j = C & 31;
    int col = (j < 16) ? (n0 + j * 8) : (2048 + n0 + (j - 16) * 8);
    bsrc[q] = w1e + (size_t)k * 4096 + col;
    bdst[q] = 18432 + k * 512 + ((j ^ (k & 7)) << 4);
  }

  auto ld = [&](int kb) {
    char* base = smem + (kb & 1) * STG1;
    size_t ako = (size_t)kb * KHALF;
#pragma unroll
    for (int q = 0; q < 2; q++) cp16(base + adst[q], asrc[q] + ako, apred[q]);
    size_t bko = (size_t)kb * KHALF * 4096;
#pragma unroll
    for (int q = 0; q < 4; q++) cp16(base + bdst[q], bsrc[q] + bko, true);
    cp_commit();
  };

  float cg[2][4][4], cu[2][4][4];
#pragma unroll
  for (int mi = 0; mi < 2; mi++)
#pragma unroll
    for (int ni = 0; ni < 4; ni++)
#pragma unroll
      for (int q = 0; q < 4; q++) { cg[mi][ni][q] = 0.f; cu[mi][ni][q] = 0.f; }

  int wm = (w & 3) * 32, wn = (w >> 2) * 32;
  int lr = lane & 7, lhalf = (lane >> 3) & 1, lci = lane >> 4;
  uint32_t krow = lhalf * 8 + lr;
  uint32_t k7 = krow & 7;
  uint32_t browoff = krow * 512;
  uint32_t cgb = wn >> 3;
  uint32_t cub = 16 + (wn >> 3);

  ld(0);

  for (int kb = 0; kb < NKB; kb++) {
    asm volatile("cp.async.wait_group 0;");
    __syncthreads();
    if (kb + 1 < NKB) ld(kb + 1);
    const char* Ab = smem + (kb & 1) * STG1;
    uint32_t Bu = sbase + (kb & 1) * STG1 + 18432;
#pragma unroll
    for (int kk = 0; kk < 4; kk++) {
      uint32_t a[2][4];
#pragma unroll
      for (int mi = 0; mi < 2; mi++) {
        uint32_t base = (wm + mi * 16 + g) * LDK + kk * 32 + tq * 4;
        a[mi][0] = lds32(Ab, base);
        a[mi][1] = lds32(Ab, base + 8 * LDK);
        a[mi][2] = lds32(Ab, base + 16);
        a[mi][3] = lds32(Ab, base + 8 * LDK + 16);
      }
      uint32_t bg[4][2], bu[4][2];
      uint32_t kkoff = Bu + kk * 8192 + browoff;
#pragma unroll
      for (int p = 0; p < 2; p++) {
        uint32_t c0 = cgb + 2 * p + lci;
        ldmx4t(bg[2 * p][0], bg[2 * p][1], bg[2 * p + 1][0], bg[2 * p + 1][1],
               kkoff + ((c0 ^ k7) << 4));
        uint32_t c1 = cub + 2 * p + lci;
        ldmx4t(bu[2 * p][0], bu[2 * p][1], bu[2 * p + 1][0], bu[2 * p + 1][1],
               kkoff + ((c1 ^ k7) << 4));
      }
#pragma unroll
      for (int ni = 0; ni < 4; ni++)
#pragma unroll
        for (int mi = 0; mi < 2; mi++) {
          mma16(cg[mi][ni], a[mi], bg[ni]);
          mma16(cu[mi][ni], a[mi], bu[ni]);
        }
    }
  }

  const float* b1e = b1 + (size_t)e * 4096;
#pragma unroll
  for (int ni = 0; ni < 4; ni++) {
    int col = n0 + wn + ni * 8 + 2 * tq;
    float bg0 = b1e[col], bg1 = b1e[col + 1];
    float bu0 = b1e[2048 + col], bu1 = b1e[2048 + col + 1];
#pragma unroll
    for (int mi = 0; mi < 2; mi++) {
#pragma unroll
      for (int rr = 0; rr < 2; rr++) {
        int rl = wm + mi * 16 + rr * 8 + g;
        if (m0 + rl >= cnt) continue;
        float gv0 = cg[mi][ni][rr * 2 + 0] + bg0;
        float gv1 = cg[mi][ni][rr * 2 + 1] + bg1;
        float uv0 = cu[mi][ni][rr * 2 + 0] + bu0;
        float uv1 = cu[mi][ni][rr * 2 + 1] + bu1;
        gv0 = fminf(gv0, LIMIT); gv1 = fminf(gv1, LIMIT);
        uv0 = fminf(fmaxf(uv0, -LIMIT), LIMIT);
        uv1 = fminf(fmaxf(uv1, -LIMIT), LIMIT);
        float a0 = (uv0 + 1.f) * gv0 / (1.f + __expf(-ALPHA * gv0));
        float a1 = (uv1 + 1.f) * gv1 / (1.f + __expf(-ALPHA * gv1));
        __half2 h = __floats2half2_rn(a0, a1);
        *(__half2*)(g_acth + ((size_t)e * TMAX + m0 + rl) * 2048 + col) = h;
      }
    }
  }
}

// ---------------- GEMM2: acts @ w2 -> g_part ----------------
// stage s at s*34816: A [128 x LDK] at +0, B [64 k-rows x 256B] at +18432
#define STG2 34816
#define SMEM2 (2 * STG2)

__global__ __launch_bounds__(256, 2) void gemm2_kernel() {
  int e = blockIdx.z;
  int cnt = g_cnt[e];
  int m0 = blockIdx.x * 128;
  if (m0 >= cnt) return;
  int n0 = blockIdx.y * 128;

  extern __shared__ __align__(16) char smem[];
  uint32_t sbase = (uint32_t)__cvta_generic_to_shared(smem);
  int tid = threadIdx.x, w = tid >> 5, lane = tid & 31;
  int g = lane >> 2, tq = lane & 3;

  const __half* acte = g_acth + (size_t)e * TMAX * 2048;
  const __half* w2h = g_w2h + (size_t)e * IDIM * HDIM;

  // A: 128 rows x 8 chunks = 1024; 4 per thread (256 threads)
  const __half* asrc[4]; uint32_t adst[4]; bool apred[4];
#pragma unroll
  for (int q = 0; q < 4; q++) {
    int idx = tid + q * 256;
    int row = idx >> 3, ch = idx & 7;
    apred[q] = (m0 + row) < cnt;
    asrc[q] = acte + (size_t)(m0 + row) * 2048 + ch * 8;
    adst[q] = row * LDK + ch * 16;
  }
  // B: 64 rows x 16 chunks = 1024; 4 per thread
  const __half* bsrc[4]; uint32_t bdst[4];
#pragma unroll
  for (int q = 0; q < 4; q++) {
    int C = tid + q * 256;
    int k = C >> 4, j = C & 15;
    bsrc[q] = w2h + (size_t)k * 2048 + n0 + j * 8;
    bdst[q] = 18432 + k * 256 + ((j ^ (k & 7)) << 4);
  }

  auto ld = [&](int kb) {
    char* base = smem + (kb & 1) * STG2;
    size_t ako = (size_t)kb * KHALF;
#pragma unroll
    for (int q = 0; q < 4; q++) cp16(base + adst[q], asrc[q] + ako, apred[q]);
    size_t bko = (size_t)kb * KHALF * 2048;
#pragma unroll
    for (int q = 0; q < 4; q++) cp16(base + bdst[q], bsrc[q] + bko, true);
    cp_commit();
  };

  float cc[2][8][4];
#pragma unroll
  for (int mi = 0; mi < 2; mi++)
#pragma unroll
    for (int ni = 0; ni < 8; ni++)
#pragma unroll
      for (int q = 0; q < 4; q++) cc[mi][ni][q] = 0.f;

  int wm = (w & 3) * 32, wn = (w >> 2) * 64;
  int lr = lane & 7, lhalf = (lane >> 3) & 1, lci = lane >> 4;
  uint32_t krow = lhalf * 8 + lr;
  uint32_t k7 = krow & 7;
  uint32_t browoff = krow * 256;
  uint32_t cb = wn >> 3;

  ld(0);

  for (int kb = 0; kb < NKB; kb++) {
    asm volatile("cp.async.wait_group 0;");
    __syncthreads();
    if (kb + 1 < NKB) ld(kb + 1);
    const char* Ab = smem + (kb & 1) * STG2;
    uint32_t Bu = sbase + (kb & 1) * STG2 + 18432;
#pragma unroll
    for (int kk = 0; kk < 4; kk++) {
      uint32_t a[2][4];
#pragma unroll
      for (int mi = 0; mi < 2; mi++) {
        uint32_t base = (wm + mi * 16 + g) * LDK + kk * 32 + tq * 4;
        a[mi][0] = lds32(Ab, base);
        a[mi][1] = lds32(Ab, base + 8 * LDK);
        a[mi][2] = lds32(Ab, base + 16);
        a[mi][3] = lds32(Ab, base + 8 * LDK + 16);
      }
      uint32_t b[8][2];
      uint32_t kkoff = Bu + kk * 4096 + browoff;
#pragma unroll
      for (int p = 0; p < 4; p++) {
        uint32_t c0 = cb + 2 * p + lci;
        ldmx4t(b[2 * p][0], b[2 * p][1], b[2 * p + 1][0], b[2 * p + 1][1],
               kkoff + ((c0 ^ k7) << 4));
      }
#pragma unroll
      for (int ni = 0; ni < 8; ni++)
#pragma unroll
        for (int mi = 0; mi < 2; mi++) mma16(cc[mi][ni], a[mi], b[ni]);
    }
  }

  float* parte = g_part + (size_t)e * TMAX * 2048;
#pragma unroll
  for (int mi = 0; mi < 2; mi++) {
#pragma unroll
    for (int rr = 0; rr < 2; rr++) {
      int rl = wm + mi * 16 + rr * 8 + g;
      if (m0 + rl >= cnt) continue;
      float* prow = parte + (size_t)(m0 + rl) * 2048 + n0;
#pragma unroll
      for (int ni = 0; ni < 8; ni++) {
        float2 v = { cc[mi][ni][rr * 2 + 0], cc[mi][ni][rr * 2 + 1] };
        *(float2*)(prow + wn + ni * 8 + 2 * tq) = v;
      }
    }
  }
}

// ---------------- gather ----------------
__global__ __launch_bounds__(256) void gather_kernel(const float* __restrict__ b2,
                                                     float* __restrict__ out) {
  int t = blockIdx.y;
  int h = blockIdx.x * 1024 + threadIdx.x * 4;
  float4 acc = {0.f, 0.f, 0.f, 0.f};
#pragma unroll
  for (int j = 0; j < TOPK; j++) {
    int sidx = g_tslot[t * TOPK + j];
    float wj = g_twt[t * TOPK + j];
    int e = sidx >> 12;
    float4 p = *(const float4*)(g_part + (size_t)sidx * 2048 + h);
    float4 b = *(const float4*)(b2 + (size_t)e * 2048 + h);
    acc.x += wj * (p.x + b.x);
    acc.y += wj * (p.y + b.y);
    acc.z += wj * (p.z + b.z);
    acc.w += wj * (p.w + b.w);
  }
  *(float4*)(out + (size_t)t * 2048 + h) = acc;
}

// ---------------- launch ----------------
extern "C" void kernel_launch(void* const* d_in, const int* in_sizes, int n_in,
                              void* d_out, int out_size) {
  (void)in_sizes; (void)n_in; (void)out_size;
  const float* hs = (const float*)d_in[0];
  const float* rw = (const float*)d_in[1];
  const float* rb = (const float*)d_in[2];
  const float* w1 = (const float*)d_in[3];
  const float* b1 = (const float*)d_in[4];
  const float* w2 = (const float*)d_in[5];
  const float* b2 = (const float*)d_in[6];
  float* out = (float*)d_out;

  void *pxh, *pw1h, *pw2h;
  cudaGetSymbolAddress(&pxh, g_xh);
  cudaGetSymbolAddress(&pw1h, g_w1h);
  cudaGetSymbolAddress(&pw2h, g_w2h);

  zero_cnt_kernel<<<1, 32>>>();
  router_kernel<<<TMAX / 8, 256>>>(hs, rw, rb);
  cvt_kernel<<<(int)(((size_t)TMAX * HDIM) / 1024), 256>>>(hs, (__half*)pxh);
  cvt_kernel<<<(int)(((size_t)NEXP * HDIM * 4096) / 1024), 256>>>(w1, (__half*)pw1h);
  cvt_kernel<<<(int)(((size_t)NEXP * IDIM * HDIM) / 1024), 256>>>(w2, (__half*)pw2h);

  cudaFuncSetAttribute(gemm1_kernel, cudaFuncAttributeMaxDynamicSharedMemorySize, SMEM1);
  cudaFuncSetAttribute(gemm2_kernel, cudaFuncAttributeMaxDynamicSharedMemorySize, SMEM2);

  dim3 g1(TMAX / 128, 16, NEXP);
  gemm1_kernel<<<g1, 512, SMEM1>>>(b1);
  dim3 g2(TMAX / 128, 16, NEXP);
  gemm2_kernel<<<g2, 256, SMEM2>>>();
  dim3 gg(2, TMAX);
  gather_kernel<<<gg, 256>>>(b2, out);
}